// round 1
// baseline (speedup 1.0000x reference)
#include <cuda_runtime.h>

#define NMAX 100000
#define EMAX 1600000

// ---------------- device scratch (no allocations allowed) ----------------
__device__ float g_deg   [NMAX];
__device__ float g_dinv  [NMAX];
__device__ float g_tmp   [NMAX * 64];
__device__ float g_h1    [NMAX * 64];
__device__ float g_h2    [NMAX * 64];
__device__ float g_logits[NMAX * 32];
__device__ float g_wts   [NMAX];
__device__ float g_pmin  [256];
__device__ float g_pmax  [256];
__device__ float g_minmax[2];
__device__ float g_acc   [33];   // [0..31] sum(e*logits), [32] sum(e)

// ---------------- degree / normalization ----------------
__global__ void deg_init_k(int n) {
    int i = blockIdx.x * blockDim.x + threadIdx.x;
    if (i < n) g_deg[i] = 1.0f;   // self-loop
}

__global__ void deg_count_k(const int* __restrict__ dstI, int e) {
    int i = blockIdx.x * blockDim.x + threadIdx.x;
    if (i < e) atomicAdd(&g_deg[dstI[i]], 1.0f);
}

__global__ void dinv_k(int n) {
    int i = blockIdx.x * blockDim.x + threadIdx.x;
    if (i < n) g_dinv[i] = rsqrtf(g_deg[i]);
}

// ---------------- tiled [n,64] @ [64,64] GEMM into g_tmp ----------------
__global__ void gemm64_k(const float* __restrict__ Xin,
                         const float* __restrict__ W,
                         int use_h1, int n) {
    __shared__ float Ws[64 * 68];   // stride 68 keeps float4 aligned, staggers banks
    __shared__ float Xs[64 * 65];
    const float* X = use_h1 ? g_h1 : Xin;
    int n0 = blockIdx.x * 64;
    int t  = threadIdx.x;
    for (int idx = t; idx < 4096; idx += 256) {
        int r = idx >> 6, c = idx & 63;
        Ws[r * 68 + c] = W[idx];
        int gn = n0 + r;
        Xs[r * 65 + c] = (gn < n) ? X[gn * 64 + c] : 0.0f;
    }
    __syncthreads();
    int nl = t >> 2;           // local node 0..63
    int g  = t & 3;            // output group 0..3 (16 outputs each)
    float acc[16];
#pragma unroll
    for (int j = 0; j < 16; j++) acc[j] = 0.0f;
#pragma unroll 4
    for (int k = 0; k < 64; k++) {
        float xv = Xs[nl * 65 + k];
        const float4* w4 = (const float4*)(Ws + k * 68 + g * 16);
        float4 a = w4[0], b = w4[1], c4 = w4[2], d = w4[3];
        acc[0]  += xv * a.x;  acc[1]  += xv * a.y;  acc[2]  += xv * a.z;  acc[3]  += xv * a.w;
        acc[4]  += xv * b.x;  acc[5]  += xv * b.y;  acc[6]  += xv * b.z;  acc[7]  += xv * b.w;
        acc[8]  += xv * c4.x; acc[9]  += xv * c4.y; acc[10] += xv * c4.z; acc[11] += xv * c4.w;
        acc[12] += xv * d.x;  acc[13] += xv * d.y;  acc[14] += xv * d.z;  acc[15] += xv * d.w;
    }
    int gn = n0 + nl;
    if (gn < n) {
        float4* yp = (float4*)(g_tmp + gn * 64 + g * 16);
        yp[0] = make_float4(acc[0],  acc[1],  acc[2],  acc[3]);
        yp[1] = make_float4(acc[4],  acc[5],  acc[6],  acc[7]);
        yp[2] = make_float4(acc[8],  acc[9],  acc[10], acc[11]);
        yp[3] = make_float4(acc[12], acc[13], acc[14], acc[15]);
    }
}

// ---------------- conv accumulator init with self-loop ----------------
__global__ void self_init_k(int which, int n) {
    int idx = blockIdx.x * blockDim.x + threadIdx.x;
    if (idx >= n * 64) return;
    int i = idx >> 6;
    float di = g_dinv[i];
    float* out = which ? g_h2 : g_h1;
    out[idx] = g_tmp[idx] * di * di;
}

// ---------------- edge scatter: out[dst] += tmp[src]*dinv[src]*dinv[dst] ----------------
__global__ void scatter_k(const int* __restrict__ srcI,
                          const int* __restrict__ dstI,
                          int which, int e) {
    int wid  = (blockIdx.x * blockDim.x + threadIdx.x) >> 5;
    int lane = threadIdx.x & 31;
    int eid  = wid * 2 + (lane >> 4);
    if (eid >= e) return;
    int c = lane & 15;
    int s = srcI[eid];
    int d = dstI[eid];
    float nrm = g_dinv[s] * g_dinv[d];
    float4 v = ((const float4*)(g_tmp + s * 64))[c];
    float* out = which ? g_h2 : g_h1;
    float* dp = out + d * 64 + c * 4;
    unsigned long long ga;
    asm("cvta.to.global.u64 %0, %1;" : "=l"(ga) : "l"(dp));
    asm volatile("red.global.add.v4.f32 [%0], {%1,%2,%3,%4};"
                 :: "l"(ga), "f"(v.x * nrm), "f"(v.y * nrm),
                    "f"(v.z * nrm), "f"(v.w * nrm) : "memory");
}

// ---------------- bias + BN(eval, mean=0,var=1) + ReLU, in place on g_h1 ----------------
__global__ void bn_relu_k(const float* __restrict__ gamma,
                          const float* __restrict__ beta,
                          const float* __restrict__ b1, int n) {
    int idx = blockIdx.x * blockDim.x + threadIdx.x;
    if (idx >= n * 64) return;
    int c = idx & 63;
    const float s = rsqrtf(1.0f + 1e-5f);
    float v = (g_h1[idx] + b1[c]) * s * gamma[c] + beta[c];
    g_h1[idx] = v > 0.0f ? v : 0.0f;
}

// ---------------- logits + softmax + entropy + wts (per node) ----------------
__global__ void logits_k(const float* __restrict__ b2,
                         const float* __restrict__ W,   // [64,32] row-major
                         const float* __restrict__ bb,  // [32]
                         int n) {
    __shared__ float Hs[64 * 65];
    __shared__ float Wl[64 * 32];
    __shared__ float Ls[64 * 33];
    int n0 = blockIdx.x * 64;
    int t  = threadIdx.x;
    for (int idx = t; idx < 2048; idx += 256) Wl[idx] = W[idx];
    for (int idx = t; idx < 4096; idx += 256) {
        int r = idx >> 6, c = idx & 63;
        int gn = n0 + r;
        Hs[r * 65 + c] = (gn < n) ? g_h2[gn * 64 + c] + b2[c] : 0.0f;
    }
    __syncthreads();
    int nl = t >> 2;   // node 0..63
    int g  = t & 3;    // output group, 8 each
    float acc[8];
#pragma unroll
    for (int j = 0; j < 8; j++) acc[j] = bb[g * 8 + j];
#pragma unroll 4
    for (int k = 0; k < 64; k++) {
        float xv = Hs[nl * 65 + k];
        const float4* w4 = (const float4*)(Wl + k * 32 + g * 8);
        float4 a = w4[0], b = w4[1];
        acc[0] += xv * a.x; acc[1] += xv * a.y; acc[2] += xv * a.z; acc[3] += xv * a.w;
        acc[4] += xv * b.x; acc[5] += xv * b.y; acc[6] += xv * b.z; acc[7] += xv * b.w;
    }
#pragma unroll
    for (int j = 0; j < 8; j++) Ls[nl * 33 + g * 8 + j] = acc[j];
    __syncthreads();
    // write raw logits out (coalesced)
    for (int idx = t; idx < 2048; idx += 256) {
        int r = idx >> 5, o = idx & 31;
        int gn = n0 + r;
        if (gn < n) g_logits[gn * 32 + o] = Ls[r * 33 + o];
    }
    // softmax + entropy per node: 8 warps, 8 nodes each
    int w = t >> 5, lane = t & 31;
    for (int r = w; r < 64; r += 8) {
        int gn = n0 + r;
        float l = Ls[r * 33 + lane];
        float m = l;
#pragma unroll
        for (int off = 16; off; off >>= 1)
            m = fmaxf(m, __shfl_xor_sync(0xffffffffu, m, off));
        float p = expf(l - m);
        float sum = p;
#pragma unroll
        for (int off = 16; off; off >>= 1)
            sum += __shfl_xor_sync(0xffffffffu, sum, off);
        p /= sum;
        float term = -p * logf(p + 1e-9f);
#pragma unroll
        for (int off = 16; off; off >>= 1)
            term += __shfl_xor_sync(0xffffffffu, term, off);
        if (lane == 0 && gn < n) g_wts[gn] = 1.0f / (term + 1e-10f);
    }
}

// ---------------- min/max reduction of wts ----------------
__global__ void mm_part_k(int n) {
    __shared__ float smn[256], smx[256];
    int t = threadIdx.x;
    float mn = 3.4e38f, mx = -3.4e38f;
    for (int i = blockIdx.x * 256 + t; i < n; i += 256 * gridDim.x) {
        float w = g_wts[i];
        mn = fminf(mn, w); mx = fmaxf(mx, w);
    }
    smn[t] = mn; smx[t] = mx;
    __syncthreads();
    for (int s = 128; s; s >>= 1) {
        if (t < s) { smn[t] = fminf(smn[t], smn[t + s]); smx[t] = fmaxf(smx[t], smx[t + s]); }
        __syncthreads();
    }
    if (t == 0) { g_pmin[blockIdx.x] = smn[0]; g_pmax[blockIdx.x] = smx[0]; }
}

__global__ void mm_final_k() {
    __shared__ float smn[256], smx[256];
    int t = threadIdx.x;
    smn[t] = g_pmin[t]; smx[t] = g_pmax[t];
    if (t < 33) g_acc[t] = 0.0f;   // zero weighted-sum accumulators
    __syncthreads();
    for (int s = 128; s; s >>= 1) {
        if (t < s) { smn[t] = fminf(smn[t], smn[t + s]); smx[t] = fmaxf(smx[t], smx[t + s]); }
        __syncthreads();
    }
    if (t == 0) { g_minmax[0] = smn[0]; g_minmax[1] = smx[0]; }
}

// ---------------- weighted sum: sum(e_i * logits_i), sum(e_i) ----------------
__global__ void wsum_k(int n) {
    __shared__ float sacc[8][33];
    int t = threadIdx.x, w = t >> 5, lane = t & 31;
    float mn = g_minmax[0];
    float den = g_minmax[1] - mn;
    float inv = den > 0.0f ? 1.0f / den : 0.0f;
    float acc = 0.0f, se = 0.0f;
    int warpG = blockIdx.x * 8 + w;
    int nwarp = gridDim.x * 8;
    for (int i = warpG; i < n; i += nwarp) {
        float e = expf((g_wts[i] - mn) * inv);   // softmax up to constant factor
        acc += e * g_logits[i * 32 + lane];
        se  += e;
    }
    sacc[w][lane] = acc;
    if (lane == 0) sacc[w][32] = se;
    __syncthreads();
    if (w == 0) {
        float a = sacc[0][lane];
#pragma unroll
        for (int r = 1; r < 8; r++) a += sacc[r][lane];
        atomicAdd(&g_acc[lane], a);
        if (lane == 0) {
            float b = sacc[0][32];
#pragma unroll
            for (int r = 1; r < 8; r++) b += sacc[r][32];
            atomicAdd(&g_acc[32], b);
        }
    }
}

// ---------------- final: (graph/sumE) @ lin3_w + lin3_b ----------------
__global__ void final_k(const float* __restrict__ w3,   // [32,64]
                        const float* __restrict__ b3,   // [64]
                        float* __restrict__ out) {
    int j = threadIdx.x;   // 0..63
    float invS = 1.0f / g_acc[32];
    float a = b3[j];
#pragma unroll
    for (int o = 0; o < 32; o++) a += (g_acc[o] * invS) * w3[o * 64 + j];
    out[j] = a;
}

// ---------------- launch ----------------
extern "C" void kernel_launch(void* const* d_in, const int* in_sizes, int n_in,
                              void* d_out, int out_size) {
    const float* x     = (const float*)d_in[0];
    const int*   ei    = (const int*)  d_in[1];
    const float* W1    = (const float*)d_in[2];
    const float* b1    = (const float*)d_in[3];
    const float* gamma = (const float*)d_in[4];
    const float* beta  = (const float*)d_in[5];
    const float* W2    = (const float*)d_in[6];
    const float* b2    = (const float*)d_in[7];
    const float* l2w   = (const float*)d_in[8];
    const float* l2b   = (const float*)d_in[9];
    const float* l3w   = (const float*)d_in[10];
    const float* l3b   = (const float*)d_in[11];
    float* out = (float*)d_out;

    int n = in_sizes[0] / 64;
    int e = in_sizes[1] / 2;
    const int* srcI = ei;
    const int* dstI = ei + e;

    int nb  = (n + 255) / 256;
    int eb  = (e + 255) / 256;
    int feb = (n * 64 + 255) / 256;
    int gb  = (n + 63) / 64;
    int sb  = (e + 15) / 16;   // 16 edges per 256-thread block

    deg_init_k <<<nb, 256>>>(n);
    deg_count_k<<<eb, 256>>>(dstI, e);
    dinv_k     <<<nb, 256>>>(n);

    // layer 1
    gemm64_k   <<<gb, 256>>>(x, W1, 0, n);
    self_init_k<<<feb, 256>>>(0, n);
    scatter_k  <<<sb, 256>>>(srcI, dstI, 0, e);
    bn_relu_k  <<<feb, 256>>>(gamma, beta, b1, n);

    // layer 2
    gemm64_k   <<<gb, 256>>>(x, W2, 1, n);
    self_init_k<<<feb, 256>>>(1, n);
    scatter_k  <<<sb, 256>>>(srcI, dstI, 1, e);

    // readout
    logits_k   <<<gb, 256>>>(b2, l2w, l2b, n);
    mm_part_k  <<<256, 256>>>(n);
    mm_final_k <<<1, 256>>>();
    wsum_k     <<<128, 256>>>(n);
    final_k    <<<1, 64>>>(l3w, l3b, out);
}

// round 3
// speedup vs baseline: 1.4937x; 1.4937x over previous
#include <cuda_runtime.h>

#define NMAX 100000

// ---------------- device scratch ----------------
__device__ float g_deg   [NMAX];
__device__ float g_dinv  [NMAX];
__device__ float g_tmp   [NMAX * 64];
__device__ float g_h1    [NMAX * 64];
__device__ float g_h2    [NMAX * 64];
__device__ float g_logits[NMAX * 32];
__device__ float g_wts   [NMAX];
__device__ float g_pmin  [256];
__device__ float g_pmax  [256];
__device__ float g_minmax[2];
__device__ float g_acc   [33];

// ---------------- degree / normalization ----------------
__global__ void deg_init_k(int n) {
    int i = blockIdx.x * blockDim.x + threadIdx.x;
    if (i < n) g_deg[i] = 1.0f;   // self-loop
}
__global__ void deg_count_k(const int* __restrict__ dstI, int e) {
    int i = blockIdx.x * blockDim.x + threadIdx.x;
    if (i < e) atomicAdd(&g_deg[dstI[i]], 1.0f);
}
__global__ void dinv_k(int n) {
    int i = blockIdx.x * blockDim.x + threadIdx.x;
    if (i < n) g_dinv[i] = rsqrtf(g_deg[i]);
}

// ---------------- fused GEMM: [128-node tile] x [64x64 W] ----------------
// Thread tile: 4 nodes x 8 outputs. X stored k-major in smem, XOR-swizzled so
// the 4-node float4 read at (k, ng) is conflict-free and W reads are warp-broadcast.
// Epilogue writes raw h -> g_tmp AND h*dinv^2 -> out_acc (self-loop init fused).
// MODE 0: X = Xin (harness input), out_acc = g_h1.
// MODE 1: X = g_h1 with bias+BN+ReLU applied while loading, out_acc = g_h2.
// NOTE: device globals must be selected IN-KERNEL (host shadow symbols are not
// device pointers — on GB300/ATS they silently read host memory).
template<int MODE>
__global__ void __launch_bounds__(256) gemm_fused_k(
    const float* __restrict__ Xin,
    const float* __restrict__ W,
    const float* __restrict__ b1,
    const float* __restrict__ gamma,
    const float* __restrict__ beta,
    int n)
{
    __shared__ float4 Xs4[64 * 32];   // 32 KB : [k][node-group swizzled]
    __shared__ float4 Ws4[64 * 16];   // 16 KB : [k][j/4]
    const float* X  = (MODE == 0) ? Xin : g_h1;
    float* out_acc  = (MODE == 0) ? g_h1 : g_h2;
    int t  = threadIdx.x;
    int n0 = blockIdx.x * 128;

    const float4* W4 = (const float4*)W;
    for (int i = t; i < 1024; i += 256) Ws4[i] = W4[i];

    const float rs = rsqrtf(1.0f + 1e-5f);
    float* Xsf = (float*)Xs4;
    for (int i = t; i < 2048; i += 256) {
        int node = i >> 4, c4 = i & 15;
        int gn = n0 + node;
        float4 v = make_float4(0.f, 0.f, 0.f, 0.f);
        if (gn < n) {
            v = ((const float4*)(X + (size_t)gn * 64))[c4];
            if (MODE == 1) {
                float4 gm = ((const float4*)gamma)[c4];
                float4 bt = ((const float4*)beta )[c4];
                float4 bb = ((const float4*)b1   )[c4];
                float a0 = rs * gm.x, a1 = rs * gm.y, a2 = rs * gm.z, a3 = rs * gm.w;
                v.x = fmaxf(fmaf(v.x + bb.x, a0, bt.x), 0.f);
                v.y = fmaxf(fmaf(v.y + bb.y, a1, bt.y), 0.f);
                v.z = fmaxf(fmaf(v.z + bb.z, a2, bt.z), 0.f);
                v.w = fmaxf(fmaf(v.w + bb.w, a3, bt.w), 0.f);
            }
        }
        int g = node >> 2, lo = node & 3;
        int sg = g ^ (c4 & 7);
        float* base = Xsf + (c4 * 4) * 128 + sg * 4 + lo;
        base[0]   = v.x;
        base[128] = v.y;
        base[256] = v.z;
        base[384] = v.w;
    }
    __syncthreads();

    int ng = t & 31;        // node group (4 nodes)
    int og = t >> 5;        // output group (8 outputs) — uniform per warp
    float acc[4][8];
#pragma unroll
    for (int i = 0; i < 4; i++)
#pragma unroll
        for (int j = 0; j < 8; j++) acc[i][j] = 0.f;

#pragma unroll 8
    for (int k = 0; k < 64; k++) {
        float4 xv = Xs4[k * 32 + (ng ^ ((k >> 2) & 7))];
        float4 w0 = Ws4[k * 16 + og * 2];
        float4 w1 = Ws4[k * 16 + og * 2 + 1];
        float xa[4] = {xv.x, xv.y, xv.z, xv.w};
        float wv[8] = {w0.x, w0.y, w0.z, w0.w, w1.x, w1.y, w1.z, w1.w};
#pragma unroll
        for (int i = 0; i < 4; i++)
#pragma unroll
            for (int j = 0; j < 8; j++)
                acc[i][j] = fmaf(xa[i], wv[j], acc[i][j]);
    }

    int nb = n0 + 4 * ng;
    if (nb < n) {
        float4 dv = *(const float4*)(g_dinv + nb);
        float ds[4] = {dv.x * dv.x, dv.y * dv.y, dv.z * dv.z, dv.w * dv.w};
#pragma unroll
        for (int i = 0; i < 4; i++) {
            int gn = nb + i;
            if (gn < n) {
                float4 r0 = make_float4(acc[i][0], acc[i][1], acc[i][2], acc[i][3]);
                float4 r1 = make_float4(acc[i][4], acc[i][5], acc[i][6], acc[i][7]);
                float4* tp = (float4*)(g_tmp + (size_t)gn * 64 + og * 8);
                tp[0] = r0; tp[1] = r1;
                float s = ds[i];
                float4* ap = (float4*)(out_acc + (size_t)gn * 64 + og * 8);
                ap[0] = make_float4(r0.x * s, r0.y * s, r0.z * s, r0.w * s);
                ap[1] = make_float4(r1.x * s, r1.y * s, r1.z * s, r1.w * s);
            }
        }
    }
}

// ---------------- edge scatter: out[dst] += tmp[src]*dinv[src]*dinv[dst] ----------------
__global__ void scatter_k(const int* __restrict__ srcI,
                          const int* __restrict__ dstI,
                          int which, int e) {
    int wid  = (blockIdx.x * blockDim.x + threadIdx.x) >> 5;
    int lane = threadIdx.x & 31;
    int eid  = wid * 2 + (lane >> 4);
    if (eid >= e) return;
    int c = lane & 15;
    int s = __ldg(srcI + eid);
    int d = __ldg(dstI + eid);
    float nrm = g_dinv[s] * g_dinv[d];
    float4 v = ((const float4*)(g_tmp + (size_t)s * 64))[c];
    float* out = which ? g_h2 : g_h1;
    float* dp = out + (size_t)d * 64 + c * 4;
    unsigned long long ga;
    asm("cvta.to.global.u64 %0, %1;" : "=l"(ga) : "l"(dp));
    asm volatile("red.global.add.v4.f32 [%0], {%1,%2,%3,%4};"
                 :: "l"(ga), "f"(v.x * nrm), "f"(v.y * nrm),
                    "f"(v.z * nrm), "f"(v.w * nrm) : "memory");
}

// ---------------- logits + softmax + entropy + wts ----------------
// 128-node tile, 128 threads, thread tile 4 nodes x 8 outputs (32 outputs total).
__global__ void __launch_bounds__(128) logits_k(
    const float* __restrict__ b2,
    const float* __restrict__ W,    // [64,32] row-major
    const float* __restrict__ bb,   // [32]
    int n)
{
    __shared__ float4 Xs4[64 * 32];  // 32 KB, reused for Ls after sync
    __shared__ float4 Wl4[64 * 8];   // 8 KB
    int t  = threadIdx.x;
    int n0 = blockIdx.x * 128;

    for (int i = t; i < 512; i += 128) Wl4[i] = ((const float4*)W)[i];

    float* Xsf = (float*)Xs4;
    for (int i = t; i < 2048; i += 128) {
        int node = i >> 4, c4 = i & 15;
        int gn = n0 + node;
        float4 v = make_float4(0.f, 0.f, 0.f, 0.f);
        if (gn < n) {
            v = ((const float4*)(g_h2 + (size_t)gn * 64))[c4];
            float4 b = ((const float4*)b2)[c4];
            v.x += b.x; v.y += b.y; v.z += b.z; v.w += b.w;
        }
        int g = node >> 2, lo = node & 3;
        int sg = g ^ (c4 & 7);
        float* base = Xsf + (c4 * 4) * 128 + sg * 4 + lo;
        base[0]   = v.x;
        base[128] = v.y;
        base[256] = v.z;
        base[384] = v.w;
    }
    __syncthreads();

    int ng = t & 31;
    int og = t >> 5;   // 0..3, uniform per warp
    float acc[4][8];
    float4 bb0 = ((const float4*)bb)[og * 2];
    float4 bb1 = ((const float4*)bb)[og * 2 + 1];
    float bj[8] = {bb0.x, bb0.y, bb0.z, bb0.w, bb1.x, bb1.y, bb1.z, bb1.w};
#pragma unroll
    for (int i = 0; i < 4; i++)
#pragma unroll
        for (int j = 0; j < 8; j++) acc[i][j] = bj[j];

#pragma unroll 8
    for (int k = 0; k < 64; k++) {
        float4 xv = Xs4[k * 32 + (ng ^ ((k >> 2) & 7))];
        float4 w0 = Wl4[k * 8 + og * 2];
        float4 w1 = Wl4[k * 8 + og * 2 + 1];
        float xa[4] = {xv.x, xv.y, xv.z, xv.w};
        float wv[8] = {w0.x, w0.y, w0.z, w0.w, w1.x, w1.y, w1.z, w1.w};
#pragma unroll
        for (int i = 0; i < 4; i++)
#pragma unroll
            for (int j = 0; j < 8; j++)
                acc[i][j] = fmaf(xa[i], wv[j], acc[i][j]);
    }
    __syncthreads();   // done reading Xs — reuse as Ls[128][33]

    float* Ls = Xsf;
#pragma unroll
    for (int i = 0; i < 4; i++)
#pragma unroll
        for (int j = 0; j < 8; j++)
            Ls[(4 * ng + i) * 33 + og * 8 + j] = acc[i][j];
    __syncthreads();

    int lane = t & 31;
    for (int r = og; r < 128; r += 4) {
        int gn = n0 + r;
        float l = Ls[r * 33 + lane];
        float m = l;
#pragma unroll
        for (int off = 16; off; off >>= 1)
            m = fmaxf(m, __shfl_xor_sync(0xffffffffu, m, off));
        float p = expf(l - m);
        float sum = p;
#pragma unroll
        for (int off = 16; off; off >>= 1)
            sum += __shfl_xor_sync(0xffffffffu, sum, off);
        p /= sum;
        float term = -p * logf(p + 1e-9f);
#pragma unroll
        for (int off = 16; off; off >>= 1)
            term += __shfl_xor_sync(0xffffffffu, term, off);
        if (gn < n) {
            g_logits[(size_t)gn * 32 + lane] = l;
            if (lane == 0) g_wts[gn] = 1.0f / (term + 1e-10f);
        }
    }
}

// ---------------- min/max reduction of wts ----------------
__global__ void mm_part_k(int n) {
    __shared__ float smn[256], smx[256];
    int t = threadIdx.x;
    float mn = 3.4e38f, mx = -3.4e38f;
    for (int i = blockIdx.x * 256 + t; i < n; i += 256 * gridDim.x) {
        float w = g_wts[i];
        mn = fminf(mn, w); mx = fmaxf(mx, w);
    }
    smn[t] = mn; smx[t] = mx;
    __syncthreads();
    for (int s = 128; s; s >>= 1) {
        if (t < s) { smn[t] = fminf(smn[t], smn[t + s]); smx[t] = fmaxf(smx[t], smx[t + s]); }
        __syncthreads();
    }
    if (t == 0) { g_pmin[blockIdx.x] = smn[0]; g_pmax[blockIdx.x] = smx[0]; }
}

__global__ void mm_final_k() {
    __shared__ float smn[256], smx[256];
    int t = threadIdx.x;
    smn[t] = g_pmin[t]; smx[t] = g_pmax[t];
    if (t < 33) g_acc[t] = 0.0f;
    __syncthreads();
    for (int s = 128; s; s >>= 1) {
        if (t < s) { smn[t] = fminf(smn[t], smn[t + s]); smx[t] = fmaxf(smx[t], smx[t + s]); }
        __syncthreads();
    }
    if (t == 0) { g_minmax[0] = smn[0]; g_minmax[1] = smx[0]; }
}

// ---------------- weighted sum ----------------
__global__ void wsum_k(int n) {
    __shared__ float sacc[8][33];
    int t = threadIdx.x, w = t >> 5, lane = t & 31;
    float mn = g_minmax[0];
    float den = g_minmax[1] - mn;
    float inv = den > 0.0f ? 1.0f / den : 0.0f;
    float acc = 0.0f, se = 0.0f;
    int warpG = blockIdx.x * 8 + w;
    int nwarp = gridDim.x * 8;
    for (int i = warpG; i < n; i += nwarp) {
        float e = expf((g_wts[i] - mn) * inv);
        acc += e * g_logits[(size_t)i * 32 + lane];
        se  += e;
    }
    sacc[w][lane] = acc;
    if (lane == 0) sacc[w][32] = se;
    __syncthreads();
    if (w == 0) {
        float a = sacc[0][lane];
#pragma unroll
        for (int r = 1; r < 8; r++) a += sacc[r][lane];
        atomicAdd(&g_acc[lane], a);
        if (lane == 0) {
            float b = sacc[0][32];
#pragma unroll
            for (int r = 1; r < 8; r++) b += sacc[r][32];
            atomicAdd(&g_acc[32], b);
        }
    }
}

// ---------------- final ----------------
__global__ void final_k(const float* __restrict__ w3,
                        const float* __restrict__ b3,
                        float* __restrict__ out) {
    int j = threadIdx.x;
    float invS = 1.0f / g_acc[32];
    float a = b3[j];
#pragma unroll
    for (int o = 0; o < 32; o++) a += (g_acc[o] * invS) * w3[o * 64 + j];
    out[j] = a;
}

// ---------------- launch ----------------
extern "C" void kernel_launch(void* const* d_in, const int* in_sizes, int n_in,
                              void* d_out, int out_size) {
    const float* x     = (const float*)d_in[0];
    const int*   ei    = (const int*)  d_in[1];
    const float* W1    = (const float*)d_in[2];
    const float* b1    = (const float*)d_in[3];
    const float* gamma = (const float*)d_in[4];
    const float* beta  = (const float*)d_in[5];
    const float* W2    = (const float*)d_in[6];
    const float* b2    = (const float*)d_in[7];
    const float* l2w   = (const float*)d_in[8];
    const float* l2b   = (const float*)d_in[9];
    const float* l3w   = (const float*)d_in[10];
    const float* l3b   = (const float*)d_in[11];
    float* out = (float*)d_out;

    int n = in_sizes[0] / 64;
    int e = in_sizes[1] / 2;
    const int* srcI = ei;
    const int* dstI = ei + e;

    int nb = (n + 255) / 256;
    int eb = (e + 255) / 256;
    int gb = (n + 127) / 128;
    int sb = (e + 15) / 16;

    deg_init_k <<<nb, 256>>>(n);
    deg_count_k<<<eb, 256>>>(dstI, e);
    dinv_k     <<<nb, 256>>>(n);

    // layer 1: gemm writes g_tmp (raw) + g_h1 (self-loop-scaled)
    gemm_fused_k<0><<<gb, 256>>>(x, W1, nullptr, nullptr, nullptr, n);
    scatter_k   <<<sb, 256>>>(srcI, dstI, 0, e);

    // layer 2: bn+relu fused into load; writes g_tmp + g_h2
    gemm_fused_k<1><<<gb, 256>>>(nullptr, W2, b1, gamma, beta, n);
    scatter_k   <<<sb, 256>>>(srcI, dstI, 1, e);

    // readout
    logits_k  <<<gb, 128>>>(b2, l2w, l2b, n);
    mm_part_k <<<256, 256>>>(n);
    mm_final_k<<<1, 256>>>();
    wsum_k    <<<128, 256>>>(n);
    final_k   <<<1, 64>>>(l3w, l3b, out);
}